// round 1
// baseline (speedup 1.0000x reference)
#include <cuda_runtime.h>

#define H 2048
#define W 2048
#define BW 32
#define BH 32
#define HALO 3
#define TW (BW + 2 * HALO)   // 38
#define TH (BH + 2 * HALO)   // 38

__global__ __launch_bounds__(1024, 2)
void plane_fit_kernel(const float* __restrict__ x, float* __restrict__ out) {
    __shared__ float tile[TH][TW];       // raw input tile with halo
    __shared__ float hbox[TH][BW];       // horizontal box sums
    __shared__ float hramp[TH][BW];      // horizontal ramp sums

    const int tid = threadIdx.y * BW + threadIdx.x;
    const int bx = blockIdx.x * BW;
    const int by = blockIdx.y * BH;

    // ---- Stage 1: load 38x38 tile with edge clamping ----
    #pragma unroll
    for (int idx = tid; idx < TH * TW; idx += BW * BH) {
        int r = idx / TW;
        int c = idx - r * TW;
        int gi = by + r - HALO;
        int gj = bx + c - HALO;
        gi = gi < 0 ? 0 : (gi > H - 1 ? H - 1 : gi);
        gj = gj < 0 ? 0 : (gj > W - 1 ? W - 1 : gj);
        tile[r][c] = x[gi * W + gj];
    }
    __syncthreads();

    // ---- Stage 2: horizontal pass (box + ramp) over 38 rows x 32 cols ----
    #pragma unroll
    for (int idx = tid; idx < TH * BW; idx += BW * BH) {
        int r = idx >> 5;          // idx / 32
        int c = idx & 31;          // idx % 32
        float s = 0.0f, rmp = 0.0f;
        #pragma unroll
        for (int d = 0; d < 7; d++) {
            float v = tile[r][c + d];
            s += v;
            rmp += (float)(d - HALO) * v;
        }
        hbox[r][c] = s;
        hramp[r][c] = rmp;
    }
    __syncthreads();

    // ---- Stage 3: vertical pass, one output pixel per thread ----
    const int tx = threadIdx.x;
    const int ty = threadIdx.y;
    float sb = 0.0f;   // box_y(box_x)   -> C2
    float sbr = 0.0f;  // box_y(ramp_x)  -> C0
    float srb = 0.0f;  // ramp_y(box_x)  -> C1
    #pragma unroll
    for (int d = 0; d < 7; d++) {
        float b = hbox[ty + d][tx];
        float rp = hramp[ty + d][tx];
        sb += b;
        sbr += rp;
        srb += (float)(d - HALO) * b;
    }

    const float inv196 = 1.0f / 196.0f;
    const float inv49 = 1.0f / 49.0f;
    float c0 = sbr * inv196;
    float c1 = srb * inv196;
    float c2 = sb * inv49;

    const int gi = by + ty;
    const int gj = bx + tx;
    float* o = out + ((long)gi * W + gj) * 3;
    o[0] = c0;
    o[1] = c1;
    o[2] = c2;
}

extern "C" void kernel_launch(void* const* d_in, const int* in_sizes, int n_in,
                              void* d_out, int out_size) {
    const float* x = (const float*)d_in[0];
    float* out = (float*)d_out;
    dim3 block(BW, BH);
    dim3 grid(W / BW, H / BH);
    plane_fit_kernel<<<grid, block>>>(x, out);
}

// round 2
// speedup vs baseline: 1.8902x; 1.8902x over previous
#include <cuda_runtime.h>

#define H 2048
#define W 2048
#define BW 32
#define BH 64
#define RPT 8            // output rows per thread
#define TROWS (BH + 6)   // 70 horizontal-sum rows per block

__global__ __launch_bounds__(256)
void plane_fit_kernel(const float* __restrict__ x, float* __restrict__ out) {
    // Interleaved horizontal sums: .x = 7-tap box, .y = 7-tap ramp
    __shared__ float2 hbr[TROWS][BW];

    const int tx = threadIdx.x;          // 0..31
    const int ty = threadIdx.y;          // 0..7
    const int tid = ty * 32 + tx;
    const int bx = blockIdx.x * BW;
    const int by = blockIdx.y * BH;

    const bool interior = (bx != 0) && (bx != W - BW) && (by != 0) && (by != H - BH);

    if (interior) {
        // ---- Horizontal pass, vectorized, straight from global (no tile smem) ----
        // Task = (row r of 70, column-group cg of 8). 4 outputs per task.
        #pragma unroll 1
        for (int t = tid; t < TROWS * 8; t += 256) {
            int r = t >> 3;
            int cg = t & 7;
            int gi = by + r - 3;                     // in-bounds (interior in y)
            const float4* p = reinterpret_cast<const float4*>(
                x + (size_t)gi * W + (bx + cg * 4 - 4));   // 16B-aligned
            float4 A = p[0], B = p[1], C = p[2];
            float v1 = A.y, v2 = A.z, v3 = A.w;
            float v4 = B.x, v5 = B.y, v6 = B.z, v7 = B.w;
            float v8 = C.x, v9 = C.y, v10 = C.z;

            float s0 = ((v1 + v2) + (v3 + v4)) + ((v5 + v6) + v7);
            float s1 = s0 - v1 + v8;
            float s2 = s1 - v2 + v9;
            float s3 = s2 - v3 + v10;

            float r0 = fmaf(3.f, v7 - v1, fmaf(2.f, v6 - v2, v5 - v3));
            float r1 = fmaf(3.f, v8 - v2, fmaf(2.f, v7 - v3, v6 - v4));
            float r2 = fmaf(3.f, v9 - v3, fmaf(2.f, v8 - v4, v7 - v5));
            float r3 = fmaf(3.f, v10 - v4, fmaf(2.f, v9 - v5, v8 - v6));

            float4* dst = reinterpret_cast<float4*>(&hbr[r][cg * 4]);
            dst[0] = make_float4(s0, r0, s1, r1);
            dst[1] = make_float4(s2, r2, s3, r3);
        }
    } else {
        // ---- Border blocks: scalar path with edge clamping ----
        #pragma unroll 1
        for (int t = tid; t < TROWS * BW; t += 256) {
            int r = t >> 5;
            int c = t & 31;
            int gi = by + r - 3;
            gi = gi < 0 ? 0 : (gi > H - 1 ? H - 1 : gi);
            const float* row = x + (size_t)gi * W;
            float s = 0.f, rmp = 0.f;
            #pragma unroll
            for (int d = 0; d < 7; d++) {
                int gj = bx + c + d - 3;
                gj = gj < 0 ? 0 : (gj > W - 1 ? W - 1 : gj);
                float v = row[gj];
                s += v;
                rmp += (float)(d - 3) * v;
            }
            hbr[r][c] = make_float2(s, rmp);
        }
    }
    __syncthreads();

    // ---- Vertical pass: each thread owns column tx, rows ty*8 .. ty*8+7 ----
    const int r0 = ty * RPT;
    float2 bh[RPT + 7];
    #pragma unroll
    for (int i = 0; i < RPT + 7; i++) bh[i] = hbr[r0 + i][tx];

    float sb = 0.f, sbr = 0.f, srb = 0.f;
    #pragma unroll
    for (int k = 0; k < 7; k++) {
        sb  += bh[k].x;
        sbr += bh[k].y;
        srb += (float)(k - 3) * bh[k].x;
    }

    const float inv196 = 1.0f / 196.0f;
    const float inv49  = 1.0f / 49.0f;
    const int gj = bx + tx;

    #pragma unroll
    for (int i = 0; i < RPT; i++) {
        int gi = by + r0 + i;
        float* o = out + ((size_t)gi * W + gj) * 3;
        o[0] = sbr * inv196;   // C0: horizontal-ramp, vertical-box
        o[1] = srb * inv196;   // C1: horizontal-box, vertical-ramp
        o[2] = sb  * inv49;    // C2: mean
        if (i < RPT - 1) {
            float bo = bh[i].x, bn = bh[i + 7].x;
            srb = srb - sb + fmaf(4.f, bo, 3.f * bn);
            sb  = sb - bo + bn;
            sbr = sbr - bh[i].y + bh[i + 7].y;
        }
    }
}

extern "C" void kernel_launch(void* const* d_in, const int* in_sizes, int n_in,
                              void* d_out, int out_size) {
    const float* x = (const float*)d_in[0];
    float* out = (float*)d_out;
    dim3 block(32, 8);
    dim3 grid(W / BW, H / BH);   // 64 x 32 = 2048 blocks
    plane_fit_kernel<<<grid, block>>>(x, out);
}

// round 3
// speedup vs baseline: 2.0981x; 1.1100x over previous
#include <cuda_runtime.h>

#define H 2048
#define W 2048
#define BW 32
#define BH 64
#define RPT 8            // output rows per thread
#define TROWS (BH + 6)   // 70 horizontal-sum rows per block

__global__ __launch_bounds__(256)
void plane_fit_kernel(const float* __restrict__ x, float* __restrict__ out) {
    // Interleaved horizontal sums: .x = 7-tap box, .y = 7-tap ramp
    __shared__ float2 hbr[TROWS][BW];

    const int tx = threadIdx.x;          // 0..31 (lane)
    const int ty = threadIdx.y;          // 0..7
    const int tid = ty * 32 + tx;
    const int bx = blockIdx.x * BW;
    const int by = blockIdx.y * BH;

    const bool interior = (bx != 0) && (bx != W - BW) && (by != 0) && (by != H - BH);

    if (interior) {
        // ---- Horizontal pass, vectorized, straight from global ----
        #pragma unroll 1
        for (int t = tid; t < TROWS * 8; t += 256) {
            int r = t >> 3;
            int cg = t & 7;
            int gi = by + r - 3;                     // in-bounds (interior in y)
            const float4* p = reinterpret_cast<const float4*>(
                x + (size_t)gi * W + (bx + cg * 4 - 4));   // 16B-aligned
            float4 A = p[0], B = p[1], C = p[2];
            float v1 = A.y, v2 = A.z, v3 = A.w;
            float v4 = B.x, v5 = B.y, v6 = B.z, v7 = B.w;
            float v8 = C.x, v9 = C.y, v10 = C.z;

            float s0 = ((v1 + v2) + (v3 + v4)) + ((v5 + v6) + v7);
            float s1 = s0 - v1 + v8;
            float s2 = s1 - v2 + v9;
            float s3 = s2 - v3 + v10;

            float r0 = fmaf(3.f, v7 - v1, fmaf(2.f, v6 - v2, v5 - v3));
            float r1 = fmaf(3.f, v8 - v2, fmaf(2.f, v7 - v3, v6 - v4));
            float r2 = fmaf(3.f, v9 - v3, fmaf(2.f, v8 - v4, v7 - v5));
            float r3 = fmaf(3.f, v10 - v4, fmaf(2.f, v9 - v5, v8 - v6));

            float4* dst = reinterpret_cast<float4*>(&hbr[r][cg * 4]);
            dst[0] = make_float4(s0, r0, s1, r1);
            dst[1] = make_float4(s2, r2, s3, r3);
        }
    } else {
        // ---- Border blocks: scalar path with edge clamping ----
        #pragma unroll 1
        for (int t = tid; t < TROWS * BW; t += 256) {
            int r = t >> 5;
            int c = t & 31;
            int gi = by + r - 3;
            gi = gi < 0 ? 0 : (gi > H - 1 ? H - 1 : gi);
            const float* row = x + (size_t)gi * W;
            float s = 0.f, rmp = 0.f;
            #pragma unroll
            for (int d = 0; d < 7; d++) {
                int gj = bx + c + d - 3;
                gj = gj < 0 ? 0 : (gj > W - 1 ? W - 1 : gj);
                float v = row[gj];
                s += v;
                rmp += (float)(d - 3) * v;
            }
            hbr[r][c] = make_float2(s, rmp);
        }
    }
    __syncthreads();

    // ---- Vertical pass: thread owns column tx, rows ty*8 .. ty*8+7 ----
    const int r0 = ty * RPT;
    float2 bh[RPT + 7];
    #pragma unroll
    for (int i = 0; i < RPT + 7; i++) bh[i] = hbr[r0 + i][tx];

    float sb = 0.f, sbr = 0.f, srb = 0.f;
    #pragma unroll
    for (int k = 0; k < 7; k++) {
        sb  += bh[k].x;
        sbr += bh[k].y;
        srb += (float)(k - 3) * bh[k].x;
    }

    const float inv196 = 1.0f / 196.0f;
    const float inv49  = 1.0f / 49.0f;

    // Warp-transpose store setup: dest lane l = 3q+m writes float4 at offset
    // 16*l in the 384B row segment; sources are lanes 4q+m and 4q+m+1.
    const int q  = tx / 3;
    const int m  = tx - 3 * q;
    const int sA = 4 * q + m;
    const int sB = sA + 1;
    const bool writer = (tx < 24);
    float* const rowbase = out + ((size_t)(by + r0) * W + bx) * 3 + tx * 4;

    #pragma unroll
    for (int i = 0; i < RPT; i++) {
        float c0 = sbr * inv196;   // horizontal-ramp, vertical-box
        float c1 = srb * inv196;   // horizontal-box, vertical-ramp
        float c2 = sb  * inv49;    // mean

        // Gather both source pixels' coefficients via shuffle
        float a0 = __shfl_sync(0xffffffffu, c0, sA);
        float a1 = __shfl_sync(0xffffffffu, c1, sA);
        float a2 = __shfl_sync(0xffffffffu, c2, sA);
        float b0 = __shfl_sync(0xffffffffu, c0, sB);
        float b1 = __shfl_sync(0xffffffffu, c1, sB);
        float b2 = __shfl_sync(0xffffffffu, c2, sB);

        float w0 = (m == 0) ? a0 : ((m == 1) ? a1 : a2);
        float w1 = (m == 0) ? a1 : ((m == 1) ? a2 : b0);
        float w2 = (m == 0) ? a2 : ((m == 1) ? b0 : b1);
        float w3 = (m == 0) ? b0 : ((m == 1) ? b1 : b2);

        if (writer) {
            *reinterpret_cast<float4*>(rowbase + (size_t)i * W * 3) =
                make_float4(w0, w1, w2, w3);
        }

        if (i < RPT - 1) {
            float bo = bh[i].x, bn = bh[i + 7].x;
            srb = srb - sb + fmaf(4.f, bo, 3.f * bn);
            sb  = sb - bo + bn;
            sbr = sbr - bh[i].y + bh[i + 7].y;
        }
    }
}

extern "C" void kernel_launch(void* const* d_in, const int* in_sizes, int n_in,
                              void* d_out, int out_size) {
    const float* x = (const float*)d_in[0];
    float* out = (float*)d_out;
    dim3 block(32, 8);
    dim3 grid(W / BW, H / BH);   // 64 x 32 = 2048 blocks
    plane_fit_kernel<<<grid, block>>>(x, out);
}